// round 9
// baseline (speedup 1.0000x reference)
#include <cuda_runtime.h>
#include <math.h>

#define NB 8
#define NH 512
#define NW 512
#define NP 32
#define HWC (NH*NW)
#define EPSF 1e-8f
#define INV2BW2 50.0f
#define NSEG 32
#define SEGROWS 16
#define SDSTRIDE 544        /* >= 512 + 32 skew: max skewed index 542 */
#define NBLK (NB*NSEG)      /* 256 */

/* ---------------- scratch (device globals) ---------------- */
__device__ float g_ex[NB*NP*NW];
__device__ float g_ey[NB*NP*NH];
__device__ float g_sx[NB*NP];
__device__ float g_sy[NB*NP];
__device__ float g_psum_part[NBLK];
__device__ float g_colseg[NB*NSEG*NW];   /* 512 KB, L2-resident */
__device__ float g_part_kl[NBLK];
__device__ float g_part_emdw[NBLK];
__device__ float g_part_emdh[NBLK];
__device__ float g_amax_pval[NBLK];
__device__ int   g_amax_pidx[NBLK];
__device__ float g_amax_tval[NBLK];
__device__ int   g_amax_tidx[NBLK];
__device__ unsigned g_arr[3];
__device__ unsigned g_dep[3];

/* grid-wide barrier. All NBLK blocks are co-resident (grid=256 <= 148*2).
   Reset by the last departing block -> correct across graph replays. */
__device__ __forceinline__ void gridbar(int i) {
    __syncthreads();
    if (threadIdx.x == 0) {
        __threadfence();
        atomicAdd(&g_arr[i], 1u);
        volatile unsigned* a = &g_arr[i];
        while (*a < (unsigned)NBLK) { __nanosleep(64); }
        __threadfence();
        unsigned d = atomicAdd(&g_dep[i], 1u);
        if (d == (unsigned)(NBLK-1)) { g_arr[i] = 0u; g_dep[i] = 0u; __threadfence(); }
    }
    __syncthreads();
}

/* fast ln(x): FMA-pipe only. ln(x)=e*ln2+ln(m), m in [2/3,4/3),
   Taylor to t^11, abs err <= 1.6e-7 */
__device__ __forceinline__ float fast_ln(float x) {
    int bi = __float_as_int(x);
    int e = (bi >> 23) - 127;
    float m = __int_as_float((bi & 0x007FFFFF) | 0x3F800000);
    if (m > 1.33333333f) { m *= 0.5f; e += 1; }
    float t = m - 1.0f;
    float p = fmaf(t, 1.0f/11.0f, -1.0f/10.0f);
    p = fmaf(t, p,  1.0f/9.0f);
    p = fmaf(t, p, -0.125f);
    p = fmaf(t, p,  1.0f/7.0f);
    p = fmaf(t, p, -1.0f/6.0f);
    p = fmaf(t, p,  0.2f);
    p = fmaf(t, p, -0.25f);
    p = fmaf(t, p,  1.0f/3.0f);
    p = fmaf(t, p, -0.5f);
    p = fmaf(t, p,  1.0f);
    return fmaf((float)e, 0.693147181f, t * p);
}

__global__ __launch_bounds__(512, 2) void k_all(const float* __restrict__ pred,
                                                const float* __restrict__ pts,
                                                const float* __restrict__ mask,
                                                float* __restrict__ out, int out_size) {
    int blk = blockIdx.x;                 /* b*NSEG+seg == factor index b*NP+n */
    int b = blk >> 5, seg = blk & 31;
    int w = threadIdx.x, lane = w & 31, wid = w >> 5;

    __shared__ float sEy[SEGROWS*NP];
    __shared__ float sD[SEGROWS*SDSTRIDE];   /* ~35 KB */
    __shared__ float sred[16];
    __shared__ int   sidx[16];
    __shared__ float sNorm[3];
    __shared__ float sPk[4*NB];              /* finalize peaks: ppx,ppy,tpx,tpy */
    __shared__ float sRes[3];

    /* ========== PHASE A: factor pair for point (b, seg) + own-tile psum ========== */
    {
        float px = pts[blk*2 + 0];
        float py = pts[blk*2 + 1];
        float c  = (float)w * (1.0f/511.0f);
        float dx = c - px, dy = c - py;
        float ex = __expf(-dx*dx*INV2BW2);
        float ey = __expf(-dy*dy*INV2BW2);
        g_ex[blk*NW + w] = ex;
        g_ey[blk*NH + w] = ey;

        float v = ex;
#pragma unroll
        for (int off = 16; off; off >>= 1) v += __shfl_xor_sync(~0u, v, off);
        if (lane == 0) sred[wid] = v;
        __syncthreads();
        if (w == 0) { float s = 0.f;
#pragma unroll
            for (int j = 0; j < 16; j++) s += sred[j];
            g_sx[blk] = s; }
        __syncthreads();
        v = ey;
#pragma unroll
        for (int off = 16; off; off >>= 1) v += __shfl_xor_sync(~0u, v, off);
        if (lane == 0) sred[wid] = v;
        __syncthreads();
        if (w == 0) { float s = 0.f;
#pragma unroll
            for (int j = 0; j < 16; j++) s += sred[j];
            g_sy[blk] = s; }
        __syncthreads();

        /* psum of own 16x512 tile (2048 float4) */
        const float4* p4 = (const float4*)(pred + (b*NH + seg*SEGROWS)*NW);
        float s = 0.f;
#pragma unroll
        for (int i = 0; i < 4; i++) {
            float4 q = p4[w + i*512];
            s += (q.x + q.y) + (q.z + q.w);
        }
#pragma unroll
        for (int off = 16; off; off >>= 1) s += __shfl_xor_sync(~0u, s, off);
        if (lane == 0) sred[wid] = s;
        __syncthreads();
        if (w == 0) { float a = 0.f;
#pragma unroll
            for (int j = 0; j < 16; j++) a += sred[j];
            g_psum_part[blk] = a; }
    }
    gridbar(0);

    /* ========== PHASE B: density + KL + EMD-W + colseg + argmax ========== */
    sEy[(w >> 5)*NP + (w & 31)] = g_ey[(b*NP + (w & 31))*NH + seg*SEGROWS + (w >> 5)];

    if (wid == 0) {                       /* normalizers: 32 partials each */
        float ps = g_psum_part[(b << 5) + lane];
        float ts = g_sx[(b << 5) + lane] * g_sy[(b << 5) + lane];
#pragma unroll
        for (int off = 16; off; off >>= 1) {
            ps += __shfl_xor_sync(~0u, ps, off);
            ts += __shfl_xor_sync(~0u, ts, off);
        }
        if (lane == 0) {
            float m = mask[b];
            sNorm[0] = m;
            sNorm[1] = 1.0f / (m*ps + (float)HWC*EPSF);
            sNorm[2] = 1.0f / (m*ts + (float)HWC*EPSF);
        }
    }

    float rex[NP];
#pragma unroll
    for (int n = 0; n < NP; n++) rex[n] = g_ex[(b*NP + n)*NW + w];
    __syncthreads();

    float m     = sNorm[0];
    float invSp = sNorm[1];
    float invSt = sNorm[2];

    float klacc = 0.f, ccol = 0.f;
    float apv = -1e30f, atv = -1e30f;
    int   api = 0, ati = 0;
    int rowbase = (b*NH + seg*SEGROWS)*NW + w;
    int skw = w + (w >> 4);

#pragma unroll 2
    for (int r = 0; r < SEGROWS; r++) {
        float p = __ldg(&pred[rowbase + r*NW]);
        float acc = 0.f;
#pragma unroll
        for (int n = 0; n < NP; n++) acc = fmaf(sEy[r*NP + n], rex[n], acc);
        float pm = p * m, tm = acc * m;
        float pn = (pm + EPSF) * invSp;
        float tn = (tm + EPSF) * invSt;
        float d  = pn - tn;
        sD[r*SDSTRIDE + skw] = d;         /* tile kept in smem; NO global diff */
        klacc = fmaf(tn, fast_ln(tn) - fast_ln(pn + EPSF), klacc);
        ccol += d;
        int fid = (seg*SEGROWS + r)*NW + w;
        if (pm > apv) { apv = pm; api = fid; }
        if (tm > atv) { atv = tm; ati = fid; }
    }
    g_colseg[blk*NW + w] = ccol;
    __syncthreads();

    /* EMD-W: warp wid scans row wid; lane owns 16 contiguous elems */
    float ewacc = 0.f;
    {
        float vals[16];
        int base = wid*SDSTRIDE + lane*17;
        float s = 0.f;
#pragma unroll
        for (int i = 0; i < 16; i++) { vals[i] = sD[base + i]; s += vals[i]; }
        float incl = s;
#pragma unroll
        for (int off = 1; off < 32; off <<= 1) {
            float u = __shfl_up_sync(~0u, incl, off);
            if (lane >= off) incl += u;
        }
        float run = incl - s;
#pragma unroll
        for (int i = 0; i < 16; i++) { run += vals[i]; ewacc += fabsf(run); }
    }

    /* block reductions */
    float v = klacc;
#pragma unroll
    for (int off = 16; off; off >>= 1) v += __shfl_xor_sync(~0u, v, off);
    if (lane == 0) sred[wid] = v;
    __syncthreads();
    if (w == 0) { float s = 0.f;
#pragma unroll
        for (int j = 0; j < 16; j++) s += sred[j];
        g_part_kl[blk] = s; }
    __syncthreads();

    v = ewacc;
#pragma unroll
    for (int off = 16; off; off >>= 1) v += __shfl_xor_sync(~0u, v, off);
    if (lane == 0) sred[wid] = v;
    __syncthreads();
    if (w == 0) { float s = 0.f;
#pragma unroll
        for (int j = 0; j < 16; j++) s += sred[j];
        g_part_emdw[blk] = s; }
    __syncthreads();

    /* argmax pred (val desc, idx asc) */
    float av = apv; int ai = api;
#pragma unroll
    for (int off = 16; off; off >>= 1) {
        float ov = __shfl_xor_sync(~0u, av, off);
        int   oi = __shfl_xor_sync(~0u, ai, off);
        if (ov > av || (ov == av && oi < ai)) { av = ov; ai = oi; }
    }
    if (lane == 0) { sred[wid] = av; sidx[wid] = ai; }
    __syncthreads();
    if (w == 0) {
        float bv = sred[0]; int bi = sidx[0];
#pragma unroll
        for (int j = 1; j < 16; j++)
            if (sred[j] > bv || (sred[j] == bv && sidx[j] < bi)) { bv = sred[j]; bi = sidx[j]; }
        g_amax_pval[blk] = bv; g_amax_pidx[blk] = bi;
    }
    __syncthreads();

    /* argmax targ */
    av = atv; ai = ati;
#pragma unroll
    for (int off = 16; off; off >>= 1) {
        float ov = __shfl_xor_sync(~0u, av, off);
        int   oi = __shfl_xor_sync(~0u, ai, off);
        if (ov > av || (ov == av && oi < ai)) { av = ov; ai = oi; }
    }
    if (lane == 0) { sred[wid] = av; sidx[wid] = ai; }
    __syncthreads();
    if (w == 0) {
        float bv = sred[0]; int bi = sidx[0];
#pragma unroll
        for (int j = 1; j < 16; j++)
            if (sred[j] > bv || (sred[j] == bv && sidx[j] < bi)) { bv = sred[j]; bi = sidx[j]; }
        g_amax_tval[blk] = bv; g_amax_tidx[blk] = bi;
    }
    gridbar(1);

    /* ========== PHASE C: EMD-H from smem tile + L2 carry ========== */
    {
        const float* cs = &g_colseg[(b*NSEG)*NW + w];
        float c0 = 0.f, c1 = 0.f, c2 = 0.f, c3 = 0.f;
#pragma unroll
        for (int s2 = 0; s2 < NSEG; s2 += 4) {
            if (s2 + 0 < seg) c0 += cs[(s2+0)*NW];
            if (s2 + 1 < seg) c1 += cs[(s2+1)*NW];
            if (s2 + 2 < seg) c2 += cs[(s2+2)*NW];
            if (s2 + 3 < seg) c3 += cs[(s2+3)*NW];
        }
        float c = (c0 + c1) + (c2 + c3);
        float acc = 0.f;
#pragma unroll
        for (int r = 0; r < SEGROWS; r++) { c += sD[r*SDSTRIDE + skw]; acc += fabsf(c); }

#pragma unroll
        for (int off = 16; off; off >>= 1) acc += __shfl_xor_sync(~0u, acc, off);
        if (lane == 0) sred[wid] = acc;
        __syncthreads();
        if (w == 0) { float s = 0.f;
#pragma unroll
            for (int j = 0; j < 16; j++) s += sred[j];
            g_part_emdh[blk] = s; }
    }
    gridbar(2);

    /* ========== FINALIZE: block 0 only ========== */
    if (blk != 0) return;
    {
        const float* srcs[3] = { g_part_kl, g_part_emdw, g_part_emdh };
        for (int k = 0; k < 3; k++) {
            float x = (w < NBLK) ? srcs[k][w] : 0.f;
#pragma unroll
            for (int off = 16; off; off >>= 1) x += __shfl_xor_sync(~0u, x, off);
            if (lane == 0) sred[wid] = x;
            __syncthreads();
            if (w == 0) { float s = 0.f;
#pragma unroll
                for (int j = 0; j < 16; j++) s += sred[j];
                sRes[k] = s; }
            __syncthreads();
        }

        /* per-batch argmax: warps 0..7 (w<256), warp wid handles batch wid */
        if (w < NBLK) {
            float av2 = g_amax_pval[w]; int ai2 = g_amax_pidx[w];
#pragma unroll
            for (int off = 16; off; off >>= 1) {
                float ov = __shfl_xor_sync(~0u, av2, off);
                int   oi = __shfl_xor_sync(~0u, ai2, off);
                if (ov > av2 || (ov == av2 && oi < ai2)) { av2 = ov; ai2 = oi; }
            }
            if (lane == 0) {
                sPk[0*NB + wid] = (float)(ai2 % NW) * (1.0f/511.0f);  /* ppx */
                sPk[1*NB + wid] = (float)(ai2 / NW) * (1.0f/511.0f);  /* ppy */
            }
            av2 = g_amax_tval[w]; ai2 = g_amax_tidx[w];
#pragma unroll
            for (int off = 16; off; off >>= 1) {
                float ov = __shfl_xor_sync(~0u, av2, off);
                int   oi = __shfl_xor_sync(~0u, ai2, off);
                if (ov > av2 || (ov == av2 && oi < ai2)) { av2 = ov; ai2 = oi; }
            }
            if (lane == 0) {
                sPk[2*NB + wid] = (float)(ai2 % NW) * (1.0f/511.0f);  /* tpx */
                sPk[3*NB + wid] = (float)(ai2 / NW) * (1.0f/511.0f);  /* tpy */
            }
        }
        __syncthreads();

        if (w == 0) {
            float loss = sRes[0] * (1.0f/(float)NB);
            float emd  = (sRes[1] + sRes[2]) * (0.5f / ((float)NB * (float)HWC));
            int cnt = 0;
            for (int bb = 0; bb < NB; bb++) {
                float dx = sPk[0*NB+bb]-sPk[2*NB+bb];
                float dy = sPk[1*NB+bb]-sPk[3*NB+bb];
                if (sqrtf(dx*dx + dy*dy) < 0.1f) cnt++;
            }
            float acc = (float)cnt * (1.0f/(float)NB);
            if (out_size > 0) out[0] = loss;
            if (out_size > 1) out[1] = emd;
            if (out_size > 2) out[2] = acc;
        }
    }
}

extern "C" void kernel_launch(void* const* d_in, const int* in_sizes, int n_in,
                              void* d_out, int out_size) {
    const float* pred = (const float*)d_in[0];   /* [8,512,512] */
    const float* pts  = (const float*)d_in[1];   /* [8,32,2]    */
    const float* mask = (const float*)d_in[2];   /* [8]         */
    float* out = (float*)d_out;

    k_all<<<NBLK, 512>>>(pred, pts, mask, out, out_size);
}

// round 10
// speedup vs baseline: 1.0620x; 1.0620x over previous
#include <cuda_runtime.h>
#include <math.h>

#define NB 8
#define NH 512
#define NW 512
#define NP 32
#define HWC (NH*NW)
#define EPSF 1e-8f
#define INV2BW2 50.0f
#define NSEG 32
#define SEGROWS 16
#define SDSTRIDE 544        /* >= 512 + 32 skew: max skewed index 542 */
#define NBLK (NB*NSEG)      /* 256 */

/* ---------------- scratch (device globals) ---------------- */
__device__ float g_ex[NB*NP*NW];
__device__ float g_ey[NB*NP*NH];
__device__ float g_sx[NB*NP];
__device__ float g_sy[NB*NP];
__device__ float g_psum_part[NBLK];
__device__ float g_colseg[NB*NSEG*NW];   /* 512 KB, L2-resident */
__device__ float g_part_kl[NBLK];
__device__ float g_part_emdw[NBLK];
__device__ float g_part_emdh[NBLK];
__device__ float g_amax_pval[NBLK];
__device__ int   g_amax_pidx[NBLK];
__device__ float g_amax_tval[NBLK];
__device__ int   g_amax_tidx[NBLK];
__device__ unsigned g_arr[3];
__device__ unsigned g_dep[3];

/* grid-wide barrier. All NBLK blocks co-resident (256 <= 148*2).
   Reset by last departer -> correct across graph replays. */
__device__ __forceinline__ void gridbar(int i) {
    __syncthreads();
    if (threadIdx.x == 0) {
        __threadfence();
        atomicAdd(&g_arr[i], 1u);
        volatile unsigned* a = &g_arr[i];
        while (*a < (unsigned)NBLK) { __nanosleep(64); }
        __threadfence();
        unsigned d = atomicAdd(&g_dep[i], 1u);
        if (d == (unsigned)(NBLK-1)) { g_arr[i] = 0u; g_dep[i] = 0u; __threadfence(); }
    }
    __syncthreads();
}

__global__ __launch_bounds__(512, 2) void k_all(const float* __restrict__ pred,
                                                const float* __restrict__ pts,
                                                const float* __restrict__ mask,
                                                float* __restrict__ out, int out_size) {
    int blk = blockIdx.x;                 /* b*NSEG+seg == factor index b*NP+n */
    int b = blk >> 5, seg = blk & 31;
    int w = threadIdx.x, lane = w & 31, wid = w >> 5;

    __shared__ float sEy[SEGROWS*NP];        /* [r][n], rows 16B-aligned */
    __shared__ float sD[SEGROWS*SDSTRIDE];   /* ~35 KB */
    __shared__ float sred[16];
    __shared__ int   sidx[16];
    __shared__ float sNorm[3];
    __shared__ float sPk[4*NB];
    __shared__ float sRes[3];

    /* ========== PHASE A: factor pair for point (b, seg) + own-tile psum ========== */
    {
        float px = pts[blk*2 + 0];
        float py = pts[blk*2 + 1];
        float c  = (float)w * (1.0f/511.0f);
        float dx = c - px, dy = c - py;
        float ex = __expf(-dx*dx*INV2BW2);
        float ey = __expf(-dy*dy*INV2BW2);
        g_ex[blk*NW + w] = ex;
        g_ey[blk*NH + w] = ey;

        float v = ex;
#pragma unroll
        for (int off = 16; off; off >>= 1) v += __shfl_xor_sync(~0u, v, off);
        if (lane == 0) sred[wid] = v;
        __syncthreads();
        if (w == 0) { float s = 0.f;
#pragma unroll
            for (int j = 0; j < 16; j++) s += sred[j];
            g_sx[blk] = s; }
        __syncthreads();
        v = ey;
#pragma unroll
        for (int off = 16; off; off >>= 1) v += __shfl_xor_sync(~0u, v, off);
        if (lane == 0) sred[wid] = v;
        __syncthreads();
        if (w == 0) { float s = 0.f;
#pragma unroll
            for (int j = 0; j < 16; j++) s += sred[j];
            g_sy[blk] = s; }
        __syncthreads();

        /* psum of own 16x512 tile */
        const float4* p4 = (const float4*)(pred + (b*NH + seg*SEGROWS)*NW);
        float s = 0.f;
#pragma unroll
        for (int i = 0; i < 4; i++) {
            float4 q = p4[w + i*512];
            s += (q.x + q.y) + (q.z + q.w);
        }
#pragma unroll
        for (int off = 16; off; off >>= 1) s += __shfl_xor_sync(~0u, s, off);
        if (lane == 0) sred[wid] = s;
        __syncthreads();
        if (w == 0) { float a = 0.f;
#pragma unroll
            for (int j = 0; j < 16; j++) a += sred[j];
            g_psum_part[blk] = a; }
    }
    gridbar(0);

    /* ========== PHASE B: density + KL + EMD-W + colseg + argmax ========== */
    sEy[(w >> 5)*NP + (w & 31)] = g_ey[(b*NP + (w & 31))*NH + seg*SEGROWS + (w >> 5)];

    if (wid == 0) {
        float ps = g_psum_part[(b << 5) + lane];
        float ts = g_sx[(b << 5) + lane] * g_sy[(b << 5) + lane];
#pragma unroll
        for (int off = 16; off; off >>= 1) {
            ps += __shfl_xor_sync(~0u, ps, off);
            ts += __shfl_xor_sync(~0u, ts, off);
        }
        if (lane == 0) {
            float m = mask[b];
            sNorm[0] = m;
            sNorm[1] = 1.0f / (m*ps + (float)HWC*EPSF);
            sNorm[2] = 1.0f / (m*ts + (float)HWC*EPSF);
        }
    }

    float rex[NP];
#pragma unroll
    for (int n = 0; n < NP; n++) rex[n] = g_ex[(b*NP + n)*NW + w];
    __syncthreads();

    float m     = sNorm[0];
    float invSp = sNorm[1];
    float invSt = sNorm[2];

    float klacc = 0.f, ccol = 0.f;
    float apv = -1e30f, atv = -1e30f;
    int   api = 0, ati = 0;
    int rowbase = (b*NH + seg*SEGROWS)*NW + w;
    int skw = w + (w >> 4);

#pragma unroll 2
    for (int r = 0; r < SEGROWS; r++) {
        float p = __ldg(&pred[rowbase + r*NW]);
        /* density: float4 broadcast LDS of ey, 2 accumulators for ILP */
        float a0 = 0.f, a1 = 0.f;
#pragma unroll
        for (int n4 = 0; n4 < NP/8; n4++) {
            float4 e0 = *(const float4*)&sEy[r*NP + n4*8 + 0];
            float4 e1 = *(const float4*)&sEy[r*NP + n4*8 + 4];
            a0 = fmaf(e0.x, rex[n4*8+0], a0);
            a0 = fmaf(e0.y, rex[n4*8+1], a0);
            a0 = fmaf(e0.z, rex[n4*8+2], a0);
            a0 = fmaf(e0.w, rex[n4*8+3], a0);
            a1 = fmaf(e1.x, rex[n4*8+4], a1);
            a1 = fmaf(e1.y, rex[n4*8+5], a1);
            a1 = fmaf(e1.z, rex[n4*8+6], a1);
            a1 = fmaf(e1.w, rex[n4*8+7], a1);
        }
        float acc = a0 + a1;
        float pm = p * m, tm = acc * m;
        float pn = (pm + EPSF) * invSp;
        float tn = (tm + EPSF) * invSt;
        float d  = pn - tn;
        sD[r*SDSTRIDE + skw] = d;
        klacc = fmaf(tn, __logf(__fdividef(tn, pn + EPSF)), klacc);
        ccol += d;
        int fid = (seg*SEGROWS + r)*NW + w;
        if (pm > apv) { apv = pm; api = fid; }
        if (tm > atv) { atv = tm; ati = fid; }
    }
    g_colseg[blk*NW + w] = ccol;
    __syncthreads();

    /* EMD-W: warp wid scans row wid; lane owns 16 contiguous elems */
    float ewacc = 0.f;
    {
        float vals[16];
        int base = wid*SDSTRIDE + lane*17;
        float s = 0.f;
#pragma unroll
        for (int i = 0; i < 16; i++) { vals[i] = sD[base + i]; s += vals[i]; }
        float incl = s;
#pragma unroll
        for (int off = 1; off < 32; off <<= 1) {
            float u = __shfl_up_sync(~0u, incl, off);
            if (lane >= off) incl += u;
        }
        float run = incl - s;
#pragma unroll
        for (int i = 0; i < 16; i++) { run += vals[i]; ewacc += fabsf(run); }
    }

    /* block reductions */
    float v = klacc;
#pragma unroll
    for (int off = 16; off; off >>= 1) v += __shfl_xor_sync(~0u, v, off);
    if (lane == 0) sred[wid] = v;
    __syncthreads();
    if (w == 0) { float s = 0.f;
#pragma unroll
        for (int j = 0; j < 16; j++) s += sred[j];
        g_part_kl[blk] = s; }
    __syncthreads();

    v = ewacc;
#pragma unroll
    for (int off = 16; off; off >>= 1) v += __shfl_xor_sync(~0u, v, off);
    if (lane == 0) sred[wid] = v;
    __syncthreads();
    if (w == 0) { float s = 0.f;
#pragma unroll
        for (int j = 0; j < 16; j++) s += sred[j];
        g_part_emdw[blk] = s; }
    __syncthreads();

    /* argmax pred (val desc, idx asc) */
    float av = apv; int ai = api;
#pragma unroll
    for (int off = 16; off; off >>= 1) {
        float ov = __shfl_xor_sync(~0u, av, off);
        int   oi = __shfl_xor_sync(~0u, ai, off);
        if (ov > av || (ov == av && oi < ai)) { av = ov; ai = oi; }
    }
    if (lane == 0) { sred[wid] = av; sidx[wid] = ai; }
    __syncthreads();
    if (w == 0) {
        float bv = sred[0]; int bi = sidx[0];
#pragma unroll
        for (int j = 1; j < 16; j++)
            if (sred[j] > bv || (sred[j] == bv && sidx[j] < bi)) { bv = sred[j]; bi = sidx[j]; }
        g_amax_pval[blk] = bv; g_amax_pidx[blk] = bi;
    }
    __syncthreads();

    /* argmax targ */
    av = atv; ai = ati;
#pragma unroll
    for (int off = 16; off; off >>= 1) {
        float ov = __shfl_xor_sync(~0u, av, off);
        int   oi = __shfl_xor_sync(~0u, ai, off);
        if (ov > av || (ov == av && oi < ai)) { av = ov; ai = oi; }
    }
    if (lane == 0) { sred[wid] = av; sidx[wid] = ai; }
    __syncthreads();
    if (w == 0) {
        float bv = sred[0]; int bi = sidx[0];
#pragma unroll
        for (int j = 1; j < 16; j++)
            if (sred[j] > bv || (sred[j] == bv && sidx[j] < bi)) { bv = sred[j]; bi = sidx[j]; }
        g_amax_tval[blk] = bv; g_amax_tidx[blk] = bi;
    }
    gridbar(1);

    /* ========== PHASE C: EMD-H from smem tile + L2 carry ========== */
    {
        const float* cs = &g_colseg[(b*NSEG)*NW + w];
        float c0 = 0.f, c1 = 0.f, c2 = 0.f, c3 = 0.f;
#pragma unroll
        for (int s2 = 0; s2 < NSEG; s2 += 4) {
            if (s2 + 0 < seg) c0 += cs[(s2+0)*NW];
            if (s2 + 1 < seg) c1 += cs[(s2+1)*NW];
            if (s2 + 2 < seg) c2 += cs[(s2+2)*NW];
            if (s2 + 3 < seg) c3 += cs[(s2+3)*NW];
        }
        float c = (c0 + c1) + (c2 + c3);
        float acc = 0.f;
#pragma unroll
        for (int r = 0; r < SEGROWS; r++) { c += sD[r*SDSTRIDE + skw]; acc += fabsf(c); }

#pragma unroll
        for (int off = 16; off; off >>= 1) acc += __shfl_xor_sync(~0u, acc, off);
        if (lane == 0) sred[wid] = acc;
        __syncthreads();
        if (w == 0) { float s = 0.f;
#pragma unroll
            for (int j = 0; j < 16; j++) s += sred[j];
            g_part_emdh[blk] = s; }
    }
    gridbar(2);

    /* ========== FINALIZE: block 0 only ========== */
    if (blk != 0) return;
    {
        const float* srcs[3] = { g_part_kl, g_part_emdw, g_part_emdh };
        for (int k = 0; k < 3; k++) {
            float x = (w < NBLK) ? srcs[k][w] : 0.f;
#pragma unroll
            for (int off = 16; off; off >>= 1) x += __shfl_xor_sync(~0u, x, off);
            if (lane == 0) sred[wid] = x;
            __syncthreads();
            if (w == 0) { float s = 0.f;
#pragma unroll
                for (int j = 0; j < 16; j++) s += sred[j];
                sRes[k] = s; }
            __syncthreads();
        }

        if (w < NBLK) {
            float av2 = g_amax_pval[w]; int ai2 = g_amax_pidx[w];
#pragma unroll
            for (int off = 16; off; off >>= 1) {
                float ov = __shfl_xor_sync(~0u, av2, off);
                int   oi = __shfl_xor_sync(~0u, ai2, off);
                if (ov > av2 || (ov == av2 && oi < ai2)) { av2 = ov; ai2 = oi; }
            }
            if (lane == 0) {
                sPk[0*NB + wid] = (float)(ai2 % NW) * (1.0f/511.0f);
                sPk[1*NB + wid] = (float)(ai2 / NW) * (1.0f/511.0f);
            }
            av2 = g_amax_tval[w]; ai2 = g_amax_tidx[w];
#pragma unroll
            for (int off = 16; off; off >>= 1) {
                float ov = __shfl_xor_sync(~0u, av2, off);
                int   oi = __shfl_xor_sync(~0u, ai2, off);
                if (ov > av2 || (ov == av2 && oi < ai2)) { av2 = ov; ai2 = oi; }
            }
            if (lane == 0) {
                sPk[2*NB + wid] = (float)(ai2 % NW) * (1.0f/511.0f);
                sPk[3*NB + wid] = (float)(ai2 / NW) * (1.0f/511.0f);
            }
        }
        __syncthreads();

        if (w == 0) {
            float loss = sRes[0] * (1.0f/(float)NB);
            float emd  = (sRes[1] + sRes[2]) * (0.5f / ((float)NB * (float)HWC));
            int cnt = 0;
            for (int bb = 0; bb < NB; bb++) {
                float dx = sPk[0*NB+bb]-sPk[2*NB+bb];
                float dy = sPk[1*NB+bb]-sPk[3*NB+bb];
                if (sqrtf(dx*dx + dy*dy) < 0.1f) cnt++;
            }
            float acc = (float)cnt * (1.0f/(float)NB);
            if (out_size > 0) out[0] = loss;
            if (out_size > 1) out[1] = emd;
            if (out_size > 2) out[2] = acc;
        }
    }
}

extern "C" void kernel_launch(void* const* d_in, const int* in_sizes, int n_in,
                              void* d_out, int out_size) {
    const float* pred = (const float*)d_in[0];   /* [8,512,512] */
    const float* pts  = (const float*)d_in[1];   /* [8,32,2]    */
    const float* mask = (const float*)d_in[2];   /* [8]         */
    float* out = (float*)d_out;

    k_all<<<NBLK, 512>>>(pred, pts, mask, out, out_size);
}

// round 11
// speedup vs baseline: 1.1481x; 1.0811x over previous
#include <cuda_runtime.h>
#include <math.h>

#define NB 8
#define NH 512
#define NW 512
#define NP 32
#define HWC (NH*NW)
#define EPSF 1e-8f
#define INV2BW2 50.0f
#define NSEG 32
#define SEGROWS 16
#define SDSTRIDE 544        /* >= 512 + 32 skew: max skewed index 542 */
#define NBLK (NB*NSEG)      /* 256 */

/* ---------------- scratch (device globals) ---------------- */
__device__ float g_ex[NB*NP*NW];
__device__ float g_ey[NB*NP*NH];
__device__ float g_sx[NB*NP];
__device__ float g_sy[NB*NP];
__device__ float g_psum_part[NBLK];
__device__ float g_colseg[NB*NSEG*NW];   /* 512 KB, L2-resident */
__device__ float g_part_kl[NBLK];
__device__ float g_part_emdw[NBLK];
__device__ float g_part_emdh[NBLK];
__device__ float g_amax_pval[NBLK];
__device__ int   g_amax_pidx[NBLK];
__device__ float g_amax_tval[NBLK];
__device__ int   g_amax_tidx[NBLK];
__device__ unsigned g_arr[3];
__device__ unsigned g_dep[3];

/* grid-wide barrier; all 256 blocks co-resident (<=148*2). */
__device__ __forceinline__ void gridbar(int i) {
    __syncthreads();
    if (threadIdx.x == 0) {
        __threadfence();
        atomicAdd(&g_arr[i], 1u);
        volatile unsigned* a = &g_arr[i];
        while (*a < (unsigned)NBLK) { __nanosleep(32); }
        __threadfence();
        unsigned d = atomicAdd(&g_dep[i], 1u);
        if (d == (unsigned)(NBLK-1)) { g_arr[i] = 0u; g_dep[i] = 0u; __threadfence(); }
    }
    __syncthreads();
}

/* packed f32x2 FMA (Blackwell FFMA2; PTX ISA 8.6+, sm_100a) */
__device__ __forceinline__ unsigned long long fma2(unsigned long long a,
                                                   unsigned long long b,
                                                   unsigned long long c) {
    unsigned long long d;
    asm("fma.rn.f32x2 %0, %1, %2, %3;" : "=l"(d) : "l"(a), "l"(b), "l"(c));
    return d;
}
__device__ __forceinline__ unsigned long long pack2(float lo, float hi) {
    unsigned long long d;
    asm("mov.b64 %0, {%1, %2};" : "=l"(d) : "f"(lo), "f"(hi));
    return d;
}
__device__ __forceinline__ float hadd2(unsigned long long v) {
    float lo, hi;
    asm("mov.b64 {%0, %1}, %2;" : "=f"(lo), "=f"(hi) : "l"(v));
    return lo + hi;
}

__global__ __launch_bounds__(512, 2) void k_all(const float* __restrict__ pred,
                                                const float* __restrict__ pts,
                                                const float* __restrict__ mask,
                                                float* __restrict__ out, int out_size) {
    int blk = blockIdx.x;                 /* b*NSEG+seg == factor index b*NP+n */
    int b = blk >> 5, seg = blk & 31;
    int w = threadIdx.x, lane = w & 31, wid = w >> 5;

    __shared__ __align__(16) float sEy[SEGROWS*NP];
    __shared__ float sD[SEGROWS*SDSTRIDE];
    __shared__ float sredA[16], sredB[16], sredC[16];
    __shared__ int   sidx[16];
    __shared__ float sNorm[3];
    __shared__ float sPk[4*NB];
    __shared__ float sRes[3];

    /* ===== PHASE A: factors + 1-D sums + own-tile psum (single sync block) ===== */
    {
        /* start pred loads early */
        const float4* p4 = (const float4*)(pred + (b*NH + seg*SEGROWS)*NW);
        float4 q0 = p4[w], q1 = p4[w+512], q2 = p4[w+1024], q3 = p4[w+1536];

        float px = pts[blk*2 + 0];
        float py = pts[blk*2 + 1];
        float c  = (float)w * (1.0f/511.0f);
        float dx = c - px, dy = c - py;
        float ex = __expf(-dx*dx*INV2BW2);
        float ey = __expf(-dy*dy*INV2BW2);
        g_ex[blk*NW + w] = ex;
        g_ey[blk*NH + w] = ey;

        float ps = ((q0.x+q0.y)+(q0.z+q0.w)) + ((q1.x+q1.y)+(q1.z+q1.w))
                 + ((q2.x+q2.y)+(q2.z+q2.w)) + ((q3.x+q3.y)+(q3.z+q3.w));
        float vx = ex, vy = ey;
#pragma unroll
        for (int off = 16; off; off >>= 1) {
            vx += __shfl_xor_sync(~0u, vx, off);
            vy += __shfl_xor_sync(~0u, vy, off);
            ps += __shfl_xor_sync(~0u, ps, off);
        }
        if (lane == 0) { sredA[wid] = vx; sredB[wid] = vy; sredC[wid] = ps; }
        __syncthreads();
        if (w == 0) {
            float sx = 0.f, sy = 0.f, sp = 0.f;
#pragma unroll
            for (int j = 0; j < 16; j++) { sx += sredA[j]; sy += sredB[j]; sp += sredC[j]; }
            g_sx[blk] = sx; g_sy[blk] = sy; g_psum_part[blk] = sp;
        }
    }
    gridbar(0);

    /* ===== PHASE B: density(FFMA2) + KL + EMD-W + colseg + argmax ===== */
    sEy[(w >> 5)*NP + (w & 31)] = g_ey[(b*NP + (w & 31))*NH + seg*SEGROWS + (w >> 5)];

    if (wid == 0) {
        float ps = g_psum_part[(b << 5) + lane];
        float ts = g_sx[(b << 5) + lane] * g_sy[(b << 5) + lane];
#pragma unroll
        for (int off = 16; off; off >>= 1) {
            ps += __shfl_xor_sync(~0u, ps, off);
            ts += __shfl_xor_sync(~0u, ts, off);
        }
        if (lane == 0) {
            float m = mask[b];
            sNorm[0] = m;
            sNorm[1] = 1.0f / (m*ps + (float)HWC*EPSF);
            sNorm[2] = 1.0f / (m*ts + (float)HWC*EPSF);
        }
    }

    /* ex column packed as 16 f32x2 pairs (pairs along n) */
    unsigned long long rexp[NP/2];
#pragma unroll
    for (int n = 0; n < NP; n += 2)
        rexp[n >> 1] = pack2(g_ex[(b*NP + n)*NW + w], g_ex[(b*NP + n + 1)*NW + w]);
    __syncthreads();

    float m     = sNorm[0];
    float invSp = sNorm[1];
    float invSt = sNorm[2];

    float klacc = 0.f, ccol = 0.f;
    float apv = -1e30f, atv = -1e30f;
    int   api = 0, ati = 0;
    int rowbase = (b*NH + seg*SEGROWS)*NW + w;
    int skw = w + (w >> 4);

#pragma unroll 2
    for (int r = 0; r < SEGROWS; r++) {
        float p = __ldg(&pred[rowbase + r*NW]);
        /* density: 8 x LDS.128 (as 2 f32x2 pairs each) -> 16 FFMA2 */
        unsigned long long a0 = 0ull, a1 = 0ull;
#pragma unroll
        for (int q = 0; q < NP/4; q++) {
            ulonglong2 e = *(const ulonglong2*)&sEy[r*NP + q*4];
            a0 = fma2(e.x, rexp[q*2 + 0], a0);
            a1 = fma2(e.y, rexp[q*2 + 1], a1);
        }
        float acc = hadd2(a0) + hadd2(a1);
        float pm = p * m, tm = acc * m;
        float pn = (pm + EPSF) * invSp;
        float tn = (tm + EPSF) * invSt;
        float d  = pn - tn;
        sD[r*SDSTRIDE + skw] = d;
        klacc = fmaf(tn, __logf(__fdividef(tn, pn + EPSF)), klacc);
        ccol += d;
        int fid = (seg*SEGROWS + r)*NW + w;
        if (pm > apv) { apv = pm; api = fid; }
        if (tm > atv) { atv = tm; ati = fid; }
    }
    g_colseg[blk*NW + w] = ccol;
    __syncthreads();

    /* EMD-W: warp wid scans row wid; lane owns 16 contiguous elems */
    float ewacc = 0.f;
    {
        float vals[16];
        int base = wid*SDSTRIDE + lane*17;
        float s = 0.f;
#pragma unroll
        for (int i = 0; i < 16; i++) { vals[i] = sD[base + i]; s += vals[i]; }
        float incl = s;
#pragma unroll
        for (int off = 1; off < 32; off <<= 1) {
            float u = __shfl_up_sync(~0u, incl, off);
            if (lane >= off) incl += u;
        }
        float run = incl - s;
#pragma unroll
        for (int i = 0; i < 16; i++) { run += vals[i]; ewacc += fabsf(run); }
    }

    /* combined block reductions: kl + emdw in one sync pass */
    {
        float v1 = klacc, v2 = ewacc;
#pragma unroll
        for (int off = 16; off; off >>= 1) {
            v1 += __shfl_xor_sync(~0u, v1, off);
            v2 += __shfl_xor_sync(~0u, v2, off);
        }
        if (lane == 0) { sredA[wid] = v1; sredB[wid] = v2; }
        __syncthreads();
        if (w == 0) {
            float s1 = 0.f, s2 = 0.f;
#pragma unroll
            for (int j = 0; j < 16; j++) { s1 += sredA[j]; s2 += sredB[j]; }
            g_part_kl[blk] = s1; g_part_emdw[blk] = s2;
        }
        __syncthreads();
    }

    /* argmax pred (val desc, idx asc) */
    float av = apv; int ai = api;
#pragma unroll
    for (int off = 16; off; off >>= 1) {
        float ov = __shfl_xor_sync(~0u, av, off);
        int   oi = __shfl_xor_sync(~0u, ai, off);
        if (ov > av || (ov == av && oi < ai)) { av = ov; ai = oi; }
    }
    if (lane == 0) { sredA[wid] = av; sidx[wid] = ai; }
    __syncthreads();
    if (w == 0) {
        float bv = sredA[0]; int bi = sidx[0];
#pragma unroll
        for (int j = 1; j < 16; j++)
            if (sredA[j] > bv || (sredA[j] == bv && sidx[j] < bi)) { bv = sredA[j]; bi = sidx[j]; }
        g_amax_pval[blk] = bv; g_amax_pidx[blk] = bi;
    }
    __syncthreads();

    /* argmax targ */
    av = atv; ai = ati;
#pragma unroll
    for (int off = 16; off; off >>= 1) {
        float ov = __shfl_xor_sync(~0u, av, off);
        int   oi = __shfl_xor_sync(~0u, ai, off);
        if (ov > av || (ov == av && oi < ai)) { av = ov; ai = oi; }
    }
    if (lane == 0) { sredA[wid] = av; sidx[wid] = ai; }
    __syncthreads();
    if (w == 0) {
        float bv = sredA[0]; int bi = sidx[0];
#pragma unroll
        for (int j = 1; j < 16; j++)
            if (sredA[j] > bv || (sredA[j] == bv && sidx[j] < bi)) { bv = sredA[j]; bi = sidx[j]; }
        g_amax_tval[blk] = bv; g_amax_tidx[blk] = bi;
    }
    gridbar(1);

    /* ===== PHASE C: EMD-H from smem tile + L2 carry ===== */
    {
        const float* cs = &g_colseg[(b*NSEG)*NW + w];
        float c0 = 0.f, c1 = 0.f, c2 = 0.f, c3 = 0.f;
#pragma unroll
        for (int s2 = 0; s2 < NSEG; s2 += 4) {
            if (s2 + 0 < seg) c0 += cs[(s2+0)*NW];
            if (s2 + 1 < seg) c1 += cs[(s2+1)*NW];
            if (s2 + 2 < seg) c2 += cs[(s2+2)*NW];
            if (s2 + 3 < seg) c3 += cs[(s2+3)*NW];
        }
        float c = (c0 + c1) + (c2 + c3);
        float acc = 0.f;
#pragma unroll
        for (int r = 0; r < SEGROWS; r++) { c += sD[r*SDSTRIDE + skw]; acc += fabsf(c); }

#pragma unroll
        for (int off = 16; off; off >>= 1) acc += __shfl_xor_sync(~0u, acc, off);
        if (lane == 0) sredA[wid] = acc;
        __syncthreads();
        if (w == 0) { float s = 0.f;
#pragma unroll
            for (int j = 0; j < 16; j++) s += sredA[j];
            g_part_emdh[blk] = s; }
    }
    gridbar(2);

    /* ===== FINALIZE: block 0 only ===== */
    if (blk != 0) return;
    {
        const float* srcs[3] = { g_part_kl, g_part_emdw, g_part_emdh };
        for (int k = 0; k < 3; k++) {
            float x = (w < NBLK) ? srcs[k][w] : 0.f;
#pragma unroll
            for (int off = 16; off; off >>= 1) x += __shfl_xor_sync(~0u, x, off);
            if (lane == 0) sredA[wid] = x;
            __syncthreads();
            if (w == 0) { float s = 0.f;
#pragma unroll
                for (int j = 0; j < 16; j++) s += sredA[j];
                sRes[k] = s; }
            __syncthreads();
        }

        if (w < NBLK) {
            float av2 = g_amax_pval[w]; int ai2 = g_amax_pidx[w];
#pragma unroll
            for (int off = 16; off; off >>= 1) {
                float ov = __shfl_xor_sync(~0u, av2, off);
                int   oi = __shfl_xor_sync(~0u, ai2, off);
                if (ov > av2 || (ov == av2 && oi < ai2)) { av2 = ov; ai2 = oi; }
            }
            if (lane == 0) {
                sPk[0*NB + wid] = (float)(ai2 % NW) * (1.0f/511.0f);
                sPk[1*NB + wid] = (float)(ai2 / NW) * (1.0f/511.0f);
            }
            av2 = g_amax_tval[w]; ai2 = g_amax_tidx[w];
#pragma unroll
            for (int off = 16; off; off >>= 1) {
                float ov = __shfl_xor_sync(~0u, av2, off);
                int   oi = __shfl_xor_sync(~0u, ai2, off);
                if (ov > av2 || (ov == av2 && oi < ai2)) { av2 = ov; ai2 = oi; }
            }
            if (lane == 0) {
                sPk[2*NB + wid] = (float)(ai2 % NW) * (1.0f/511.0f);
                sPk[3*NB + wid] = (float)(ai2 / NW) * (1.0f/511.0f);
            }
        }
        __syncthreads();

        if (w == 0) {
            float loss = sRes[0] * (1.0f/(float)NB);
            float emd  = (sRes[1] + sRes[2]) * (0.5f / ((float)NB * (float)HWC));
            int cnt = 0;
            for (int bb = 0; bb < NB; bb++) {
                float dx = sPk[0*NB+bb]-sPk[2*NB+bb];
                float dy = sPk[1*NB+bb]-sPk[3*NB+bb];
                if (sqrtf(dx*dx + dy*dy) < 0.1f) cnt++;
            }
            float acc = (float)cnt * (1.0f/(float)NB);
            if (out_size > 0) out[0] = loss;
            if (out_size > 1) out[1] = emd;
            if (out_size > 2) out[2] = acc;
        }
    }
}

extern "C" void kernel_launch(void* const* d_in, const int* in_sizes, int n_in,
                              void* d_out, int out_size) {
    const float* pred = (const float*)d_in[0];   /* [8,512,512] */
    const float* pts  = (const float*)d_in[1];   /* [8,32,2]    */
    const float* mask = (const float*)d_in[2];   /* [8]         */
    float* out = (float*)d_out;

    k_all<<<NBLK, 512>>>(pred, pts, mask, out, out_size);
}

// round 13
// speedup vs baseline: 1.1631x; 1.0131x over previous
#include <cuda_runtime.h>
#include <math.h>

#define NB 8
#define NH 512
#define NW 512
#define NP 32
#define HWC (NH*NW)
#define EPSF 1e-8f
#define INV2BW2 50.0f
#define NSEG 32
#define SEGROWS 16
#define SDSTRIDE 544        /* >= 512 + 32 skew: max skewed index 542 */
#define NBLK (NB*NSEG)      /* 256 */

typedef unsigned long long u64;

/* ---------------- scratch (device globals) ---------------- */
__device__ float g_ex[NB*NP*NW];
__device__ float g_ey[NB*NP*NH];
__device__ float g_colseg[NB*NSEG*NW];   /* 512 KB, L2-resident */
__device__ u64 g_tsum_fx[NB];            /* fixed-point 2^32 accumulators */
__device__ u64 g_psum_fx[NB];
__device__ u64 g_kl_fx, g_ew_fx, g_eh_fx;
__device__ u64 g_pkP[NB], g_pkT[NB];     /* packed argmax keys */
__device__ unsigned g_arr0[NB], g_arr1[NB], g_done;

/* fixed-point (scale 2^32), exact integer atomics -> deterministic */
__device__ __forceinline__ u64 to_fx(float x) {
    return (u64)__double2ll_rn((double)x * 4294967296.0);
}
__device__ __forceinline__ float from_fx(u64 v) {
    return (float)((double)(long long)v * (1.0/4294967296.0));
}

/* packed f32x2 FMA (Blackwell FFMA2) */
__device__ __forceinline__ u64 fma2(u64 a, u64 b, u64 c) {
    u64 d; asm("fma.rn.f32x2 %0, %1, %2, %3;" : "=l"(d) : "l"(a), "l"(b), "l"(c)); return d;
}
__device__ __forceinline__ u64 pack2(float lo, float hi) {
    u64 d; asm("mov.b64 %0, {%1, %2};" : "=l"(d) : "f"(lo), "f"(hi)); return d;
}
__device__ __forceinline__ float hadd2(u64 v) {
    float lo, hi; asm("mov.b64 {%0, %1}, %2;" : "=f"(lo), "=f"(hi) : "l"(v)); return lo + hi;
}

/* argmax key: val>=0 so float bits monotone; ~fid gives min-idx tie-break */
__device__ __forceinline__ u64 mkkey(float v, int fid) {
    return ((u64)__float_as_uint(v) << 32) | (u64)(0xFFFFFFFFu - (unsigned)fid);
}

__global__ __launch_bounds__(512, 2) void k_all(const float* __restrict__ pred,
                                                const float* __restrict__ pts,
                                                const float* __restrict__ mask,
                                                float* __restrict__ out, int out_size) {
    int blk = blockIdx.x;                 /* b*NSEG+seg == factor index b*NP+n */
    int b = blk >> 5, seg = blk & 31;
    int w = threadIdx.x, lane = w & 31, wid = w >> 5;

    __shared__ __align__(16) float sEy[SEGROWS*NP];
    __shared__ float sD[SEGROWS*SDSTRIDE];
    __shared__ float sredA[16], sredB[16], sredC[16];
    __shared__ u64   sredK[16], sredK2[16];
    __shared__ float sNorm[3];
    __shared__ int   sLast;

    /* ===== PHASE A: own point's factors + 1-D sums + own-tile psum ===== */
    {
        const float4* p4 = (const float4*)(pred + (b*NH + seg*SEGROWS)*NW);
        float4 q0 = p4[w], q1 = p4[w+512], q2 = p4[w+1024], q3 = p4[w+1536];

        float px = pts[blk*2 + 0];
        float py = pts[blk*2 + 1];
        float c  = (float)w * (1.0f/511.0f);
        float dx = c - px, dy = c - py;
        float ex = __expf(-dx*dx*INV2BW2);
        float ey = __expf(-dy*dy*INV2BW2);
        g_ex[blk*NW + w] = ex;
        g_ey[blk*NH + w] = ey;

        float ps = ((q0.x+q0.y)+(q0.z+q0.w)) + ((q1.x+q1.y)+(q1.z+q1.w))
                 + ((q2.x+q2.y)+(q2.z+q2.w)) + ((q3.x+q3.y)+(q3.z+q3.w));
        float vx = ex, vy = ey;
#pragma unroll
        for (int off = 16; off; off >>= 1) {
            vx += __shfl_xor_sync(~0u, vx, off);
            vy += __shfl_xor_sync(~0u, vy, off);
            ps += __shfl_xor_sync(~0u, ps, off);
        }
        if (lane == 0) { sredA[wid] = vx; sredB[wid] = vy; sredC[wid] = ps; }
        __syncthreads();
        if (w == 0) {
            float sx = 0.f, sy = 0.f, sp = 0.f;
#pragma unroll
            for (int j = 0; j < 16; j++) { sx += sredA[j]; sy += sredB[j]; sp += sredC[j]; }
            atomicAdd(&g_tsum_fx[b], to_fx(sx * sy));
            atomicAdd(&g_psum_fx[b], to_fx(sp));
            __threadfence();
            atomicAdd(&g_arr0[b], 1u);
            /* wait for the 32 siblings of this batch only */
            volatile unsigned* a0 = &g_arr0[b];
            while (*a0 < (unsigned)NSEG) __nanosleep(32);
            __threadfence();
            float ts = from_fx(*(volatile u64*)&g_tsum_fx[b]);
            float pp = from_fx(*(volatile u64*)&g_psum_fx[b]);
            float mm = mask[b];
            sNorm[0] = mm;
            sNorm[1] = 1.0f / (mm*pp + (float)HWC*EPSF);
            sNorm[2] = 1.0f / (mm*ts + (float)HWC*EPSF);
        }
    }
    __syncthreads();

    /* ===== PHASE B: density(FFMA2) + KL + EMD-W + colseg + argmax ===== */
    sEy[(w >> 5)*NP + (w & 31)] = g_ey[(b*NP + (w & 31))*NH + seg*SEGROWS + (w >> 5)];

    u64 rexp[NP/2];
#pragma unroll
    for (int n = 0; n < NP; n += 2)
        rexp[n >> 1] = pack2(g_ex[(b*NP + n)*NW + w], g_ex[(b*NP + n + 1)*NW + w]);
    __syncthreads();

    float m     = sNorm[0];
    float invSp = sNorm[1];
    float invSt = sNorm[2];

    float klacc = 0.f, ccol = 0.f;
    float apv = -1e30f, atv = -1e30f;
    int   api = 0, ati = 0;
    int rowbase = (b*NH + seg*SEGROWS)*NW + w;
    int skw = w + (w >> 4);

#pragma unroll 2
    for (int r = 0; r < SEGROWS; r++) {
        float p = __ldg(&pred[rowbase + r*NW]);
        u64 a0 = 0ull, a1 = 0ull;
#pragma unroll
        for (int q = 0; q < NP/4; q++) {
            ulonglong2 e = *(const ulonglong2*)&sEy[r*NP + q*4];
            a0 = fma2(e.x, rexp[q*2 + 0], a0);
            a1 = fma2(e.y, rexp[q*2 + 1], a1);
        }
        float acc = hadd2(a0) + hadd2(a1);
        float pm = p * m, tm = acc * m;
        float pn = (pm + EPSF) * invSp;
        float tn = (tm + EPSF) * invSt;
        float d  = pn - tn;
        sD[r*SDSTRIDE + skw] = d;
        klacc = fmaf(tn, __logf(__fdividef(tn, pn + EPSF)), klacc);
        ccol += d;
        int fid = (seg*SEGROWS + r)*NW + w;
        if (pm > apv) { apv = pm; api = fid; }
        if (tm > atv) { atv = tm; ati = fid; }
    }
    g_colseg[blk*NW + w] = ccol;
    __syncthreads();

    /* EMD-W: warp wid scans row wid; lane owns 16 contiguous elems */
    float ewacc = 0.f;
    {
        float vals[16];
        int base = wid*SDSTRIDE + lane*17;
        float s = 0.f;
#pragma unroll
        for (int i = 0; i < 16; i++) { vals[i] = sD[base + i]; s += vals[i]; }
        float incl = s;
#pragma unroll
        for (int off = 1; off < 32; off <<= 1) {
            float u = __shfl_up_sync(~0u, incl, off);
            if (lane >= off) incl += u;
        }
        float run = incl - s;
#pragma unroll
        for (int i = 0; i < 16; i++) { run += vals[i]; ewacc += fabsf(run); }
    }

    /* block reductions: kl + emdw (floats) and both argmax keys (u64) in 2 passes */
    {
        float v1 = klacc, v2 = ewacc;
        u64 kP = mkkey(apv, api), kT = mkkey(atv, ati);
#pragma unroll
        for (int off = 16; off; off >>= 1) {
            v1 += __shfl_xor_sync(~0u, v1, off);
            v2 += __shfl_xor_sync(~0u, v2, off);
            u64 oP = __shfl_xor_sync(~0u, kP, off);
            u64 oT = __shfl_xor_sync(~0u, kT, off);
            if (oP > kP) kP = oP;
            if (oT > kT) kT = oT;
        }
        if (lane == 0) { sredA[wid] = v1; sredB[wid] = v2; sredK[wid] = kP; sredK2[wid] = kT; }
        __syncthreads();
        if (w == 0) {
            float s1 = 0.f, s2 = 0.f;
            u64 bP = sredK[0], bT = sredK2[0];
#pragma unroll
            for (int j = 0; j < 16; j++) {
                s1 += sredA[j]; s2 += sredB[j];
                if (j && sredK[j]  > bP) bP = sredK[j];
                if (j && sredK2[j] > bT) bT = sredK2[j];
            }
            atomicAdd(&g_kl_fx, to_fx(s1));
            atomicAdd(&g_ew_fx, to_fx(s2));
            atomicMax(&g_pkP[b], bP);
            atomicMax(&g_pkT[b], bT);
            __threadfence();
            atomicAdd(&g_arr1[b], 1u);
            volatile unsigned* a1p = &g_arr1[b];
            while (*a1p < (unsigned)NSEG) __nanosleep(32);
            __threadfence();
        }
    }
    __syncthreads();

    /* ===== PHASE C: EMD-H from smem tile + L2 carry ===== */
    {
        const float* cs = &g_colseg[(b*NSEG)*NW + w];
        float c0 = 0.f, c1 = 0.f, c2 = 0.f, c3 = 0.f;
#pragma unroll
        for (int s2 = 0; s2 < NSEG; s2 += 4) {
            if (s2 + 0 < seg) c0 += cs[(s2+0)*NW];
            if (s2 + 1 < seg) c1 += cs[(s2+1)*NW];
            if (s2 + 2 < seg) c2 += cs[(s2+2)*NW];
            if (s2 + 3 < seg) c3 += cs[(s2+3)*NW];
        }
        float c = (c0 + c1) + (c2 + c3);
        float acc = 0.f;
#pragma unroll
        for (int r = 0; r < SEGROWS; r++) { c += sD[r*SDSTRIDE + skw]; acc += fabsf(c); }

#pragma unroll
        for (int off = 16; off; off >>= 1) acc += __shfl_xor_sync(~0u, acc, off);
        if (lane == 0) sredA[wid] = acc;
        __syncthreads();
        if (w == 0) {
            float s = 0.f;
#pragma unroll
            for (int j = 0; j < 16; j++) s += sredA[j];
            atomicAdd(&g_eh_fx, to_fx(s));
            __threadfence();
            unsigned t = atomicAdd(&g_done, 1u);
            sLast = (t == (unsigned)(NBLK-1)) ? 1 : 0;
        }
    }
    __syncthreads();

    /* ===== FINALIZE: last-done block only ===== */
    if (sLast && w == 0) {
        __threadfence();
        float loss = from_fx(*(volatile u64*)&g_kl_fx) * (1.0f/(float)NB);
        float emd  = (from_fx(*(volatile u64*)&g_ew_fx) + from_fx(*(volatile u64*)&g_eh_fx))
                     * (0.5f / ((float)NB * (float)HWC));
        int cnt = 0;
        for (int bb = 0; bb < NB; bb++) {
            unsigned fp = 0xFFFFFFFFu - (unsigned)(*(volatile u64*)&g_pkP[bb] & 0xFFFFFFFFull);
            unsigned ft = 0xFFFFFFFFu - (unsigned)(*(volatile u64*)&g_pkT[bb] & 0xFFFFFFFFull);
            float ppx = (float)(fp % NW) * (1.0f/511.0f);
            float ppy = (float)(fp / NW) * (1.0f/511.0f);
            float tpx = (float)(ft % NW) * (1.0f/511.0f);
            float tpy = (float)(ft / NW) * (1.0f/511.0f);
            float dx = ppx - tpx, dy = ppy - tpy;
            if (sqrtf(dx*dx + dy*dy) < 0.1f) cnt++;
        }
        float acc = (float)cnt * (1.0f/(float)NB);
        if (out_size > 0) out[0] = loss;
        if (out_size > 1) out[1] = emd;
        if (out_size > 2) out[2] = acc;
        /* reset state for next graph replay (all other blocks are done) */
        g_kl_fx = 0ull; g_ew_fx = 0ull; g_eh_fx = 0ull;
        g_done = 0u;
#pragma unroll
        for (int bb = 0; bb < NB; bb++) {
            g_tsum_fx[bb] = 0ull; g_psum_fx[bb] = 0ull;
            g_pkP[bb] = 0ull;     g_pkT[bb] = 0ull;
            g_arr0[bb] = 0u;      g_arr1[bb] = 0u;
        }
        __threadfence();
    }
}

extern "C" void kernel_launch(void* const* d_in, const int* in_sizes, int n_in,
                              void* d_out, int out_size) {
    const float* pred = (const float*)d_in[0];   /* [8,512,512] */
    const float* pts  = (const float*)d_in[1];   /* [8,32,2]    */
    const float* mask = (const float*)d_in[2];   /* [8]         */
    float* out = (float*)d_out;

    k_all<<<NBLK, 512>>>(pred, pts, mask, out, out_size);
}